// round 6
// baseline (speedup 1.0000x reference)
#include <cuda_runtime.h>
#include <cstdint>
#include <cstddef>

#define F 128
#define N_MAX 100000
#define E_MAX 1600000
#define NB_MAX 128   // ceil(N_MAX/1024) = 98

typedef unsigned long long u64;

// ------------------------- static scratch (no allocs) ----------------------
__device__ __align__(16) float g_H[(size_t)N_MAX * F];          // X@W+b
__device__ unsigned long long g_edge[E_MAX];                    // packed (val<<32 | col), CSR-ordered
__device__ int g_count[N_MAX];                                  // per-row degree (histogram)
__device__ int g_offset[N_MAX + 1];                             // CSR row offsets
__device__ int g_woff[N_MAX];                                   // write cursors for placement
__device__ int g_part[NB_MAX];                                  // scan block partials

// ------------------------- f32x2 packed FMA helpers ------------------------
__device__ __forceinline__ u64 pack2(float lo, float hi)
{
    u64 r;
    asm("mov.b64 %0, {%1, %2};" : "=l"(r) : "f"(lo), "f"(hi));
    return r;
}
__device__ __forceinline__ void fma2(u64& d, u64 a, u64 b)
{
    asm("fma.rn.f32x2 %0, %1, %2, %0;" : "+l"(d) : "l"(a), "l"(b));
}
__device__ __forceinline__ void add2(u64& d, u64 a)
{
    asm("add.rn.f32x2 %0, %0, %1;" : "+l"(d) : "l"(a));
}
__device__ __forceinline__ float2 unpack2(u64 v)
{
    float2 f;
    asm("mov.b64 {%0, %1}, %2;" : "=f"(f.x), "=f"(f.y) : "l"(v));
    return f;
}

// ---------------------------------------------------------------------------
// zero g_count (kernel, not memset: keep capture launches-only)
// ---------------------------------------------------------------------------
__global__ void __launch_bounds__(256) zero_count_kernel(int N)
{
    int i = blockIdx.x * blockDim.x + threadIdx.x;
    if (i < N) g_count[i] = 0;
}

// ---------------------------------------------------------------------------
// Fused: GEMM (blocks [0, gemm_blocks)) + row histogram (tail blocks).
// GEMM: H[N,128] = X[N,128] @ W[128,128] + b[128]
//   BM=256, BN=128, BK=8, 256 threads, 16x8 thread tile, packed f32x2 FMA.
//   Accumulator pairs ADJACENT ROWS so the A operand pair comes straight out
//   of an LDS.128 register quad (no packing); only B needs dup-packs.
//   LDS/FMA ratio 0.1875 float/FMA < crossbar limit 0.25 -> FMA2-issue-bound.
// ---------------------------------------------------------------------------
__global__ void __launch_bounds__(256, 1) gemm_hist_kernel(
    const float* __restrict__ X, const float* __restrict__ W,
    const float* __restrict__ bias, const int* __restrict__ rows,
    int N, int E, int gemm_blocks)
{
    if ((int)blockIdx.x >= gemm_blocks) {
        // ---- histogram part (backfills SMs as GEMM waves drain) ----
        int e = ((int)blockIdx.x - gemm_blocks) * 256 + threadIdx.x;
        if (e < E) atomicAdd(&g_count[__ldg(rows + e)], 1);
        return;
    }

    // ---- GEMM part ----
    __shared__ __align__(16) float Xs[8][256];   // [k][row]  8KB
    __shared__ __align__(16) float Ws[8][128];   // [k][col]  4KB

    const int tid  = threadIdx.x;
    const int tcol = tid & 15;        // 0..15 -> cols tcol*8 .. +7
    const int trow = tid >> 4;        // 0..15 -> rows trow*16 .. +15
    const int row0 = blockIdx.x * 256;

    u64 acc2[8][8];   // [row-pair p][col j] = (row 2p, row 2p+1) at col j
#pragma unroll
    for (int p = 0; p < 8; p++)
#pragma unroll
        for (int j = 0; j < 8; j++) acc2[p][j] = 0ull;

    // loader indices: X -> each thread loads 1 row x 8 k (2 float4)
    const int wk = tid >> 5;          // 0..7
    const int wn = (tid & 31) * 4;    // 0..124

    for (int k0 = 0; k0 < F; k0 += 8) {
        // W tile
        float4 w4 = *(const float4*)(W + (size_t)(k0 + wk) * F + wn);
        *(float4*)&Ws[wk][wn] = w4;
        // X tile: row = tid, k = k0..k0+7, transposed into [k][row]
        {
            int grow = row0 + tid;
            float4 xa = make_float4(0.f, 0.f, 0.f, 0.f);
            float4 xb = make_float4(0.f, 0.f, 0.f, 0.f);
            if (grow < N) {
                xa = *(const float4*)(X + (size_t)grow * F + k0);
                xb = *(const float4*)(X + (size_t)grow * F + k0 + 4);
            }
            Xs[0][tid] = xa.x; Xs[1][tid] = xa.y;
            Xs[2][tid] = xa.z; Xs[3][tid] = xa.w;
            Xs[4][tid] = xb.x; Xs[5][tid] = xb.y;
            Xs[6][tid] = xb.z; Xs[7][tid] = xb.w;
        }
        __syncthreads();

#pragma unroll
        for (int kk = 0; kk < 8; kk++) {
            // A: 16 rows = 4 x LDS.128 -> aligned reg quads; row-pairs are
            // adjacent register pairs, directly usable as f32x2 operands.
            float4 a0 = *(const float4*)&Xs[kk][trow * 16 + 0];
            float4 a1 = *(const float4*)&Xs[kk][trow * 16 + 4];
            float4 a2 = *(const float4*)&Xs[kk][trow * 16 + 8];
            float4 a3 = *(const float4*)&Xs[kk][trow * 16 + 12];
            u64 ap[8];
            ap[0] = pack2(a0.x, a0.y); ap[1] = pack2(a0.z, a0.w);
            ap[2] = pack2(a1.x, a1.y); ap[3] = pack2(a1.z, a1.w);
            ap[4] = pack2(a2.x, a2.y); ap[5] = pack2(a2.z, a2.w);
            ap[6] = pack2(a3.x, a3.y); ap[7] = pack2(a3.z, a3.w);
            // B: 8 cols = 2 x LDS.128; dup-pack each scalar (alu pipe)
            float4 b0 = *(const float4*)&Ws[kk][tcol * 8];
            float4 b1 = *(const float4*)&Ws[kk][tcol * 8 + 4];
            u64 bp[8];
            bp[0] = pack2(b0.x, b0.x); bp[1] = pack2(b0.y, b0.y);
            bp[2] = pack2(b0.z, b0.z); bp[3] = pack2(b0.w, b0.w);
            bp[4] = pack2(b1.x, b1.x); bp[5] = pack2(b1.y, b1.y);
            bp[6] = pack2(b1.z, b1.z); bp[7] = pack2(b1.w, b1.w);
#pragma unroll
            for (int p = 0; p < 8; p++)
#pragma unroll
                for (int j = 0; j < 8; j++)
                    fma2(acc2[p][j], ap[p], bp[j]);
        }
        __syncthreads();
    }

    // bias (dup-packed, added to both rows of each pair)
    {
        float4 bv0 = *(const float4*)(bias + tcol * 8);
        float4 bv1 = *(const float4*)(bias + tcol * 8 + 4);
        u64 bvp[8] = {
            pack2(bv0.x, bv0.x), pack2(bv0.y, bv0.y),
            pack2(bv0.z, bv0.z), pack2(bv0.w, bv0.w),
            pack2(bv1.x, bv1.x), pack2(bv1.y, bv1.y),
            pack2(bv1.z, bv1.z), pack2(bv1.w, bv1.w) };
#pragma unroll
        for (int p = 0; p < 8; p++)
#pragma unroll
            for (int j = 0; j < 8; j++)
                add2(acc2[p][j], bvp[j]);
    }

#pragma unroll
    for (int p = 0; p < 8; p++) {
        int r0 = row0 + trow * 16 + 2 * p;
        float2 c0 = unpack2(acc2[p][0]);
        float2 c1 = unpack2(acc2[p][1]);
        float2 c2 = unpack2(acc2[p][2]);
        float2 c3 = unpack2(acc2[p][3]);
        float2 c4 = unpack2(acc2[p][4]);
        float2 c5 = unpack2(acc2[p][5]);
        float2 c6 = unpack2(acc2[p][6]);
        float2 c7 = unpack2(acc2[p][7]);
        if (r0 < N) {
            float4 lo0 = make_float4(c0.x, c1.x, c2.x, c3.x);
            float4 lo1 = make_float4(c4.x, c5.x, c6.x, c7.x);
            *(float4*)(g_H + (size_t)r0 * F + tcol * 8)     = lo0;
            *(float4*)(g_H + (size_t)r0 * F + tcol * 8 + 4) = lo1;
        }
        if (r0 + 1 < N) {
            float4 hi0 = make_float4(c0.y, c1.y, c2.y, c3.y);
            float4 hi1 = make_float4(c4.y, c5.y, c6.y, c7.y);
            *(float4*)(g_H + (size_t)(r0 + 1) * F + tcol * 8)     = hi0;
            *(float4*)(g_H + (size_t)(r0 + 1) * F + tcol * 8 + 4) = hi1;
        }
    }
}

// ---------------------------------------------------------------------------
// CSR build: scans + placement
// ---------------------------------------------------------------------------
__global__ void __launch_bounds__(1024) scan_partial_kernel(int N)
{
    int i = blockIdx.x * 1024 + threadIdx.x;
    int v = (i < N) ? g_count[i] : 0;
    int lane = threadIdx.x & 31, wid = threadIdx.x >> 5;

    int x = v;
#pragma unroll
    for (int d = 1; d < 32; d <<= 1) {
        int y = __shfl_up_sync(0xffffffffu, x, d);
        if (lane >= d) x += y;
    }
    __shared__ int wsum[32];
    if (lane == 31) wsum[wid] = x;
    __syncthreads();
    if (wid == 0) {
        int w = wsum[lane];
#pragma unroll
        for (int d = 1; d < 32; d <<= 1) {
            int y = __shfl_up_sync(0xffffffffu, w, d);
            if (lane >= d) w += y;
        }
        wsum[lane] = w;
    }
    __syncthreads();
    int base = wid ? wsum[wid - 1] : 0;
    int incl = base + x;
    if (i < N) g_offset[i] = incl - v;           // block-local exclusive
    if (threadIdx.x == 1023) g_part[blockIdx.x] = incl;
}

__global__ void __launch_bounds__(128) scan_tops_kernel(int NB)
{
    __shared__ int s[128];
    int t = threadIdx.x;
    s[t] = (t < NB) ? g_part[t] : 0;
    __syncthreads();
#pragma unroll
    for (int d = 1; d < 128; d <<= 1) {
        int y = (t >= d) ? s[t - d] : 0;
        __syncthreads();
        s[t] += y;
        __syncthreads();
    }
    if (t < NB) g_part[t] = t ? s[t - 1] : 0;    // exclusive
}

__global__ void __launch_bounds__(1024) scan_add_kernel(int N, int E)
{
    int i = blockIdx.x * 1024 + threadIdx.x;
    if (i < N) {
        int o = g_offset[i] + g_part[i >> 10];
        g_offset[i] = o;
        g_woff[i]   = o;
    }
    if (i == 0) g_offset[N] = E;
}

__global__ void place_kernel(const int* __restrict__ rows,
                             const int* __restrict__ cols,
                             const float* __restrict__ vals, int E)
{
    int e = blockIdx.x * blockDim.x + threadIdx.x;
    if (e >= E) return;
    int r = __ldg(rows + e);
    int p = atomicAdd(&g_woff[r], 1);
    unsigned long long packed =
        ((unsigned long long)__float_as_uint(__ldg(vals + e)) << 32) |
        (unsigned)__ldg(cols + e);
    g_edge[p] = packed;
}

// ---------------------------------------------------------------------------
// threefry2x32-partitionable bits for element index j (key = (0,42))
// ---------------------------------------------------------------------------
__device__ __forceinline__ unsigned tf_bits(unsigned j)
{
    const unsigned ks0 = 0u, ks1 = 42u;
    const unsigned ks2 = 0x1BD11BDAu ^ ks0 ^ ks1;
    unsigned x0 = ks0;          // hi32(counter) = 0
    unsigned x1 = j + ks1;
#define TF_R(d) { x0 += x1; x1 = __funnelshift_l(x1, x1, (d)); x1 ^= x0; }
    TF_R(13) TF_R(15) TF_R(26) TF_R(6)
    x0 += ks1; x1 += ks2 + 1u;
    TF_R(17) TF_R(29) TF_R(16) TF_R(24)
    x0 += ks2; x1 += ks0 + 2u;
    TF_R(13) TF_R(15) TF_R(26) TF_R(6)
    x0 += ks0; x1 += ks1 + 3u;
    TF_R(17) TF_R(29) TF_R(16) TF_R(24)
    x0 += ks1; x1 += ks2 + 4u;
    TF_R(13) TF_R(15) TF_R(26) TF_R(6)
    x0 += ks2; x1 += ks0 + 5u;
#undef TF_R
    return x0 ^ x1;
}

__device__ __forceinline__ float drop_apply(float h, unsigned j)
{
    float u = __uint_as_float((tf_bits(j) >> 9) | 0x3f800000u) - 1.0f;
    return (u < 0.9f) ? h * (1.0f / 0.9f) : 0.0f;
}

// ---------------------------------------------------------------------------
// Gather + ReLU + dropout: warp per row.
// ---------------------------------------------------------------------------
__global__ void __launch_bounds__(256) gather_kernel(float* __restrict__ out, int N)
{
    int warp = (blockIdx.x * blockDim.x + threadIdx.x) >> 5;
    int lane = threadIdx.x & 31;
    if (warp >= N) return;
    const int row   = warp;
    const int start = g_offset[row];
    const int end   = g_offset[row + 1];

    float4 acc = make_float4(0.f, 0.f, 0.f, 0.f);

    for (int b = start; b < end; b += 32) {
        int e = b + lane;
        unsigned long long ev = (e < end) ? g_edge[e] : 0ull;
        int cnt = min(32, end - b);
        int i = 0;
        for (; i + 1 < cnt; i += 2) {
            unsigned long long e0 = __shfl_sync(0xffffffffu, ev, i);
            unsigned long long e1 = __shfl_sync(0xffffffffu, ev, i + 1);
            int   c0 = (int)(unsigned)e0;
            int   c1 = (int)(unsigned)e1;
            float v0 = __uint_as_float((unsigned)(e0 >> 32));
            float v1 = __uint_as_float((unsigned)(e1 >> 32));
            float4 m0 = *(const float4*)(g_H + (size_t)c0 * F + lane * 4);
            float4 m1 = *(const float4*)(g_H + (size_t)c1 * F + lane * 4);
            acc.x = fmaf(m0.x, v0, acc.x); acc.y = fmaf(m0.y, v0, acc.y);
            acc.z = fmaf(m0.z, v0, acc.z); acc.w = fmaf(m0.w, v0, acc.w);
            acc.x = fmaf(m1.x, v1, acc.x); acc.y = fmaf(m1.y, v1, acc.y);
            acc.z = fmaf(m1.z, v1, acc.z); acc.w = fmaf(m1.w, v1, acc.w);
        }
        if (i < cnt) {
            unsigned long long e0 = __shfl_sync(0xffffffffu, ev, i);
            int   c0 = (int)(unsigned)e0;
            float v0 = __uint_as_float((unsigned)(e0 >> 32));
            float4 m0 = *(const float4*)(g_H + (size_t)c0 * F + lane * 4);
            acc.x = fmaf(m0.x, v0, acc.x); acc.y = fmaf(m0.y, v0, acc.y);
            acc.z = fmaf(m0.z, v0, acc.z); acc.w = fmaf(m0.w, v0, acc.w);
        }
    }

    acc.x = fmaxf(acc.x, 0.f); acc.y = fmaxf(acc.y, 0.f);
    acc.z = fmaxf(acc.z, 0.f); acc.w = fmaxf(acc.w, 0.f);

    unsigned j0 = (unsigned)row * F + lane * 4;
    acc.x = drop_apply(acc.x, j0 + 0);
    acc.y = drop_apply(acc.y, j0 + 1);
    acc.z = drop_apply(acc.z, j0 + 2);
    acc.w = drop_apply(acc.w, j0 + 3);

    *(float4*)(out + (size_t)row * F + lane * 4) = acc;
}

// ---------------------------------------------------------------------------
extern "C" void kernel_launch(void* const* d_in, const int* in_sizes, int n_in,
                              void* d_out, int out_size)
{
    const float* X    = (const float*)d_in[0];
    const float* W    = (const float*)d_in[1];
    const float* bias = (const float*)d_in[2];
    const int*   rows = (const int*)d_in[3];
    const int*   cols = (const int*)d_in[4];
    const float* vals = (const float*)d_in[5];
    float* out = (float*)d_out;

    const int N = in_sizes[0] / F;      // 100000
    const int E = in_sizes[3];          // 1600000
    const int NB = (N + 1023) / 1024;   // 98

    // zero degree histogram
    zero_count_kernel<<<(N + 255) / 256, 256>>>(N);

    // fused H = X@W + b  AND  row histogram (tail blocks)
    {
        int gemm_blocks = (N + 255) / 256;
        int hist_blocks = (E + 255) / 256;
        gemm_hist_kernel<<<gemm_blocks + hist_blocks, 256>>>(
            X, W, bias, rows, N, E, gemm_blocks);
    }

    // CSR offsets + placement
    scan_partial_kernel<<<NB, 1024>>>(N);
    scan_tops_kernel<<<1, 128>>>(NB);
    scan_add_kernel<<<NB, 1024>>>(N, E);
    place_kernel<<<(E + 255) / 256, 256>>>(rows, cols, vals, E);

    // fused gather + relu + dropout
    {
        int grid = (N * 32 + 255) / 256;
        gather_kernel<<<grid, 256>>>(out, N);
    }
}

// round 9
// speedup vs baseline: 1.0719x; 1.0719x over previous
#include <cuda_runtime.h>
#include <cstdint>
#include <cstddef>

#define F 128
#define N_MAX 100000
#define E_MAX 1600000
#define NB_MAX 128   // ceil(N_MAX/1024) = 98

// ------------------------- static scratch (no allocs) ----------------------
__device__ __align__(16) float g_H[(size_t)N_MAX * F];          // X@W+b
__device__ unsigned long long g_edge[E_MAX];                    // packed (val<<32 | col), CSR-ordered
__device__ int g_count[N_MAX];                                  // per-row degree (histogram)
__device__ int g_offset[N_MAX + 1];                             // CSR row offsets
__device__ int g_woff[N_MAX];                                   // write cursors for placement
__device__ int g_part[NB_MAX];                                  // scan block partials

// ---------------------------------------------------------------------------
// zero g_count (kernel, not memset: keep capture launches-only)
// ---------------------------------------------------------------------------
__global__ void __launch_bounds__(256) zero_count_kernel(int N)
{
    int i = blockIdx.x * blockDim.x + threadIdx.x;
    if (i < N) g_count[i] = 0;
}

// ------------------------- tf32 helpers ------------------------------------
// cvt.rna.tf32.f32 requires a .b32 destination -> return as unsigned bits.
__device__ __forceinline__ unsigned to_tf32_bits(float x)
{
    unsigned r;
    asm("cvt.rna.tf32.f32 %0, %1;" : "=r"(r) : "f"(x));
    return r;
}

__device__ __forceinline__ void mma_tf32(
    float& c0, float& c1, float& c2, float& c3,
    unsigned a0, unsigned a1, unsigned a2, unsigned a3,
    unsigned b0, unsigned b1)
{
    asm("mma.sync.aligned.m16n8k8.row.col.f32.tf32.tf32.f32 "
        "{%0,%1,%2,%3}, {%4,%5,%6,%7}, {%8,%9}, {%0,%1,%2,%3};"
        : "+f"(c0), "+f"(c1), "+f"(c2), "+f"(c3)
        : "r"(a0), "r"(a1), "r"(a2), "r"(a3), "r"(b0), "r"(b1));
}

// ---------------------------------------------------------------------------
// Fused: GEMM (blocks [0, gemm_blocks)) + row histogram (tail blocks).
// GEMM: H[N,128] = X[N,128] @ W[128,128] + b[128] via 3xtf32 mma.sync
//   (fp32-class accuracy: A = Abig + Asmall, W = Wbig + Wsmall;
//    D += Asmall*Wbig + Abig*Wsmall + Abig*Wbig)
//   Block tile: BM=64, BN=128, BK=16. 8 warps (2x4), 32x32 per warp.
// ---------------------------------------------------------------------------
__global__ void __launch_bounds__(256) gemm_hist_kernel(
    const float* __restrict__ X, const float* __restrict__ W,
    const float* __restrict__ bias, const int* __restrict__ rows,
    int N, int E, int gemm_blocks)
{
    if ((int)blockIdx.x >= gemm_blocks) {
        // ---- histogram part (backfills SMs as GEMM waves drain) ----
        int e = ((int)blockIdx.x - gemm_blocks) * 256 + threadIdx.x;
        if (e < E) atomicAdd(&g_count[__ldg(rows + e)], 1);
        return;
    }

    // ---- GEMM part ----
    // pads chosen so fragment loads are conflict-free.
    __shared__ unsigned Xb[64][20], Xsm[64][20];     // 5.1 KB x2
    __shared__ unsigned Wb[16][136], Wsm[16][136];   // 8.7 KB x2

    const int tid  = threadIdx.x;
    const int wid  = tid >> 5;
    const int lane = tid & 31;
    const int g    = lane >> 2;     // groupID 0..7
    const int tg   = lane & 3;      // threadID_in_group 0..3
    const int wm   = wid >> 2;      // 0..1  (warp row: 32 rows each)
    const int wn   = wid & 3;       // 0..3  (warp col: 32 cols each)
    const int row0 = blockIdx.x * 64;

    float C[2][4][4];               // [sub_m][sub_n][frag]
#pragma unroll
    for (int s = 0; s < 2; s++)
#pragma unroll
        for (int t = 0; t < 4; t++)
#pragma unroll
            for (int q = 0; q < 4; q++) C[s][t][q] = 0.f;

    // loader indices
    const int xrow = tid >> 2;          // 0..63
    const int xk   = (tid & 3) * 4;     // 0,4,8,12
    const int wkr  = tid >> 4;          // 0..15
    const int wnc  = (tid & 15) * 8;    // 0..120

    for (int ko = 0; ko < 8; ko++) {
        const int k0 = ko * 16;
        // --- load X tile 64x16, split big/small ---
        {
            int grow = row0 + xrow;
            float4 x4 = make_float4(0.f, 0.f, 0.f, 0.f);
            if (grow < N) x4 = *(const float4*)(X + (size_t)grow * F + k0 + xk);
            float v[4] = {x4.x, x4.y, x4.z, x4.w};
#pragma unroll
            for (int i = 0; i < 4; i++) {
                unsigned big = to_tf32_bits(v[i]);
                Xb [xrow][xk + i] = big;
                Xsm[xrow][xk + i] = to_tf32_bits(v[i] - __uint_as_float(big));
            }
        }
        // --- load W tile 16x128, split big/small ---
        {
            const float* wp = W + (size_t)(k0 + wkr) * F + wnc;
            float4 w0 = *(const float4*)(wp);
            float4 w1 = *(const float4*)(wp + 4);
            float v[8] = {w0.x, w0.y, w0.z, w0.w, w1.x, w1.y, w1.z, w1.w};
#pragma unroll
            for (int i = 0; i < 8; i++) {
                unsigned big = to_tf32_bits(v[i]);
                Wb [wkr][wnc + i] = big;
                Wsm[wkr][wnc + i] = to_tf32_bits(v[i] - __uint_as_float(big));
            }
        }
        __syncthreads();

#pragma unroll
        for (int kk = 0; kk < 2; kk++) {
            const int kb = kk * 8 + tg;
            // A fragments (2 sub-tiles of 16 rows)
            unsigned ab[2][4], as_[2][4];
#pragma unroll
            for (int s = 0; s < 2; s++) {
                int r0 = wm * 32 + s * 16 + g;
                int r1 = r0 + 8;
                ab[s][0]  = Xb [r0][kb];
                ab[s][1]  = Xb [r1][kb];
                ab[s][2]  = Xb [r0][kb + 4];
                ab[s][3]  = Xb [r1][kb + 4];
                as_[s][0] = Xsm[r0][kb];
                as_[s][1] = Xsm[r1][kb];
                as_[s][2] = Xsm[r0][kb + 4];
                as_[s][3] = Xsm[r1][kb + 4];
            }
            // B fragments (4 sub-tiles of 8 cols)
            unsigned bb[4][2], bs[4][2];
#pragma unroll
            for (int t = 0; t < 4; t++) {
                int n = wn * 32 + t * 8 + g;
                bb[t][0] = Wb [kb][n];
                bb[t][1] = Wb [kb + 4][n];
                bs[t][0] = Wsm[kb][n];
                bs[t][1] = Wsm[kb + 4][n];
            }
#pragma unroll
            for (int s = 0; s < 2; s++)
#pragma unroll
                for (int t = 0; t < 4; t++) {
                    mma_tf32(C[s][t][0], C[s][t][1], C[s][t][2], C[s][t][3],
                             as_[s][0], as_[s][1], as_[s][2], as_[s][3],
                             bb[t][0], bb[t][1]);
                    mma_tf32(C[s][t][0], C[s][t][1], C[s][t][2], C[s][t][3],
                             ab[s][0], ab[s][1], ab[s][2], ab[s][3],
                             bs[t][0], bs[t][1]);
                    mma_tf32(C[s][t][0], C[s][t][1], C[s][t][2], C[s][t][3],
                             ab[s][0], ab[s][1], ab[s][2], ab[s][3],
                             bb[t][0], bb[t][1]);
                }
        }
        __syncthreads();
    }

    // epilogue: bias + store (C frag: row g/g+8, cols tg*2, tg*2+1)
#pragma unroll
    for (int t = 0; t < 4; t++) {
        int col = wn * 32 + t * 8 + tg * 2;
        float2 bv = *(const float2*)(bias + col);
#pragma unroll
        for (int s = 0; s < 2; s++) {
            int r0 = row0 + wm * 32 + s * 16 + g;
            int r1 = r0 + 8;
            if (r0 < N) {
                float2 o = make_float2(C[s][t][0] + bv.x, C[s][t][1] + bv.y);
                *(float2*)(g_H + (size_t)r0 * F + col) = o;
            }
            if (r1 < N) {
                float2 o = make_float2(C[s][t][2] + bv.x, C[s][t][3] + bv.y);
                *(float2*)(g_H + (size_t)r1 * F + col) = o;
            }
        }
    }
}

// ---------------------------------------------------------------------------
// CSR build: scans + placement
// ---------------------------------------------------------------------------
__global__ void __launch_bounds__(1024) scan_partial_kernel(int N)
{
    int i = blockIdx.x * 1024 + threadIdx.x;
    int v = (i < N) ? g_count[i] : 0;
    int lane = threadIdx.x & 31, wid = threadIdx.x >> 5;

    int x = v;
#pragma unroll
    for (int d = 1; d < 32; d <<= 1) {
        int y = __shfl_up_sync(0xffffffffu, x, d);
        if (lane >= d) x += y;
    }
    __shared__ int wsum[32];
    if (lane == 31) wsum[wid] = x;
    __syncthreads();
    if (wid == 0) {
        int w = wsum[lane];
#pragma unroll
        for (int d = 1; d < 32; d <<= 1) {
            int y = __shfl_up_sync(0xffffffffu, w, d);
            if (lane >= d) w += y;
        }
        wsum[lane] = w;
    }
    __syncthreads();
    int base = wid ? wsum[wid - 1] : 0;
    int incl = base + x;
    if (i < N) g_offset[i] = incl - v;           // block-local exclusive
    if (threadIdx.x == 1023) g_part[blockIdx.x] = incl;
}

__global__ void __launch_bounds__(128) scan_tops_kernel(int NB)
{
    __shared__ int s[128];
    int t = threadIdx.x;
    s[t] = (t < NB) ? g_part[t] : 0;
    __syncthreads();
#pragma unroll
    for (int d = 1; d < 128; d <<= 1) {
        int y = (t >= d) ? s[t - d] : 0;
        __syncthreads();
        s[t] += y;
        __syncthreads();
    }
    if (t < NB) g_part[t] = t ? s[t - 1] : 0;    // exclusive
}

__global__ void __launch_bounds__(1024) scan_add_kernel(int N, int E)
{
    int i = blockIdx.x * 1024 + threadIdx.x;
    if (i < N) {
        int o = g_offset[i] + g_part[i >> 10];
        g_offset[i] = o;
        g_woff[i]   = o;
    }
    if (i == 0) g_offset[N] = E;
}

__global__ void place_kernel(const int* __restrict__ rows,
                             const int* __restrict__ cols,
                             const float* __restrict__ vals, int E)
{
    int e = blockIdx.x * blockDim.x + threadIdx.x;
    if (e >= E) return;
    int r = __ldg(rows + e);
    int p = atomicAdd(&g_woff[r], 1);
    unsigned long long packed =
        ((unsigned long long)__float_as_uint(__ldg(vals + e)) << 32) |
        (unsigned)__ldg(cols + e);
    g_edge[p] = packed;
}

// ---------------------------------------------------------------------------
// threefry2x32-partitionable bits for element index j (key = (0,42))
// ---------------------------------------------------------------------------
__device__ __forceinline__ unsigned tf_bits(unsigned j)
{
    const unsigned ks0 = 0u, ks1 = 42u;
    const unsigned ks2 = 0x1BD11BDAu ^ ks0 ^ ks1;
    unsigned x0 = ks0;          // hi32(counter) = 0
    unsigned x1 = j + ks1;
#define TF_R(d) { x0 += x1; x1 = __funnelshift_l(x1, x1, (d)); x1 ^= x0; }
    TF_R(13) TF_R(15) TF_R(26) TF_R(6)
    x0 += ks1; x1 += ks2 + 1u;
    TF_R(17) TF_R(29) TF_R(16) TF_R(24)
    x0 += ks2; x1 += ks0 + 2u;
    TF_R(13) TF_R(15) TF_R(26) TF_R(6)
    x0 += ks0; x1 += ks1 + 3u;
    TF_R(17) TF_R(29) TF_R(16) TF_R(24)
    x0 += ks1; x1 += ks2 + 4u;
    TF_R(13) TF_R(15) TF_R(26) TF_R(6)
    x0 += ks2; x1 += ks0 + 5u;
#undef TF_R
    return x0 ^ x1;
}

__device__ __forceinline__ float drop_apply(float h, unsigned j)
{
    float u = __uint_as_float((tf_bits(j) >> 9) | 0x3f800000u) - 1.0f;
    return (u < 0.9f) ? h * (1.0f / 0.9f) : 0.0f;
}

// ---------------------------------------------------------------------------
// Gather + ReLU + dropout: warp per row.
// ---------------------------------------------------------------------------
__global__ void __launch_bounds__(256) gather_kernel(float* __restrict__ out, int N)
{
    int warp = (blockIdx.x * blockDim.x + threadIdx.x) >> 5;
    int lane = threadIdx.x & 31;
    if (warp >= N) return;
    const int row   = warp;
    const int start = g_offset[row];
    const int end   = g_offset[row + 1];

    float4 acc = make_float4(0.f, 0.f, 0.f, 0.f);

    for (int b = start; b < end; b += 32) {
        int e = b + lane;
        unsigned long long ev = (e < end) ? g_edge[e] : 0ull;
        int cnt = min(32, end - b);
        int i = 0;
        for (; i + 1 < cnt; i += 2) {
            unsigned long long e0 = __shfl_sync(0xffffffffu, ev, i);
            unsigned long long e1 = __shfl_sync(0xffffffffu, ev, i + 1);
            int   c0 = (int)(unsigned)e0;
            int   c1 = (int)(unsigned)e1;
            float v0 = __uint_as_float((unsigned)(e0 >> 32));
            float v1 = __uint_as_float((unsigned)(e1 >> 32));
            float4 m0 = *(const float4*)(g_H + (size_t)c0 * F + lane * 4);
            float4 m1 = *(const float4*)(g_H + (size_t)c1 * F + lane * 4);
            acc.x = fmaf(m0.x, v0, acc.x); acc.y = fmaf(m0.y, v0, acc.y);
            acc.z = fmaf(m0.z, v0, acc.z); acc.w = fmaf(m0.w, v0, acc.w);
            acc.x = fmaf(m1.x, v1, acc.x); acc.y = fmaf(m1.y, v1, acc.y);
            acc.z = fmaf(m1.z, v1, acc.z); acc.w = fmaf(m1.w, v1, acc.w);
        }
        if (i < cnt) {
            unsigned long long e0 = __shfl_sync(0xffffffffu, ev, i);
            int   c0 = (int)(unsigned)e0;
            float v0 = __uint_as_float((unsigned)(e0 >> 32));
            float4 m0 = *(const float4*)(g_H + (size_t)c0 * F + lane * 4);
            acc.x = fmaf(m0.x, v0, acc.x); acc.y = fmaf(m0.y, v0, acc.y);
            acc.z = fmaf(m0.z, v0, acc.z); acc.w = fmaf(m0.w, v0, acc.w);
        }
    }

    acc.x = fmaxf(acc.x, 0.f); acc.y = fmaxf(acc.y, 0.f);
    acc.z = fmaxf(acc.z, 0.f); acc.w = fmaxf(acc.w, 0.f);

    unsigned j0 = (unsigned)row * F + lane * 4;
    acc.x = drop_apply(acc.x, j0 + 0);
    acc.y = drop_apply(acc.y, j0 + 1);
    acc.z = drop_apply(acc.z, j0 + 2);
    acc.w = drop_apply(acc.w, j0 + 3);

    *(float4*)(out + (size_t)row * F + lane * 4) = acc;
}

// ---------------------------------------------------------------------------
extern "C" void kernel_launch(void* const* d_in, const int* in_sizes, int n_in,
                              void* d_out, int out_size)
{
    const float* X    = (const float*)d_in[0];
    const float* W    = (const float*)d_in[1];
    const float* bias = (const float*)d_in[2];
    const int*   rows = (const int*)d_in[3];
    const int*   cols = (const int*)d_in[4];
    const float* vals = (const float*)d_in[5];
    float* out = (float*)d_out;

    const int N = in_sizes[0] / F;      // 100000
    const int E = in_sizes[3];          // 1600000
    const int NB = (N + 1023) / 1024;   // 98

    // zero degree histogram
    zero_count_kernel<<<(N + 255) / 256, 256>>>(N);

    // fused H = X@W + b (3xtf32 tensor cores)  AND  row histogram (tail blocks)
    {
        int gemm_blocks = (N + 63) / 64;        // 1563
        int hist_blocks = (E + 255) / 256;      // 6250
        gemm_hist_kernel<<<gemm_blocks + hist_blocks, 256>>>(
            X, W, bias, rows, N, E, gemm_blocks);
    }

    // CSR offsets + placement
    scan_partial_kernel<<<NB, 1024>>>(N);
    scan_tops_kernel<<<1, 128>>>(NB);
    scan_add_kernel<<<NB, 1024>>>(N, E);
    place_kernel<<<(E + 255) / 256, 256>>>(rows, cols, vals, E);

    // fused gather + relu + dropout
    {
        int grid = (N * 32 + 255) / 256;
        gather_kernel<<<grid, 256>>>(out, N);
    }
}

// round 13
// speedup vs baseline: 1.1868x; 1.1072x over previous
#include <cuda_runtime.h>
#include <cstdint>
#include <cstddef>

#define F 128
#define N_MAX 100000
#define E_MAX 1600000
#define NB_MAX 128   // ceil(N_MAX/1024) = 98

typedef unsigned long long u64;

// ------------------------- static scratch (no allocs) ----------------------
__device__ __align__(16) float g_H[(size_t)N_MAX * F];          // X@W+b
__device__ unsigned long long g_edge[E_MAX];                    // packed (val<<32 | col), CSR-ordered
__device__ int g_count[N_MAX];                                  // degree histogram (zero-invariant)
__device__ int g_offset[N_MAX + 1];                             // CSR row offsets
__device__ int g_woff[N_MAX];                                   // placement cursors
__device__ int g_part[NB_MAX];                                  // scan block partials

// ------------------------- f32x2 packed FMA helpers ------------------------
__device__ __forceinline__ u64 pack2(float lo, float hi)
{
    u64 r;
    asm("mov.b64 %0, {%1, %2};" : "=l"(r) : "f"(lo), "f"(hi));
    return r;
}
__device__ __forceinline__ void fma2(u64& d, u64 a, u64 b)
{
    asm("fma.rn.f32x2 %0, %1, %2, %0;" : "+l"(d) : "l"(a), "l"(b));
}
__device__ __forceinline__ float2 unpack2(u64 v)
{
    float2 f;
    asm("mov.b64 {%0, %1}, %2;" : "=f"(f.x), "=f"(f.y) : "l"(v));
    return f;
}

// ---------------------------------------------------------------------------
// Fused: GEMM (blocks [0, gemm_blocks)) + row histogram (tail blocks).
// GEMM: H[N,128] = X[N,128] @ W[128,128] + b[128]
//   BM=128, BN=128, BK=8, 256 threads, 8x8 thread tile, packed f32x2 FMA.
//   (FFMA-roofline-bound; no tensor path: toolchain targets compute_100,
//    tcgen05 unavailable, legacy HMMA ~= FFMA speed on this part.)
// Hist tail: 4 edges/thread via int4 loads (atomic-bound; fewer LDGs).
// ---------------------------------------------------------------------------
__global__ void __launch_bounds__(256) gemm_hist_kernel(
    const float* __restrict__ X, const float* __restrict__ W,
    const float* __restrict__ bias, const int* __restrict__ rows,
    int N, int E, int gemm_blocks)
{
    if ((int)blockIdx.x >= gemm_blocks) {
        // ---- histogram part (backfills SMs as GEMM waves drain) ----
        int e = (((int)blockIdx.x - gemm_blocks) * 256 + threadIdx.x) * 4;
        if (e + 3 < E) {
            int4 r4 = __ldg((const int4*)(rows + e));
            atomicAdd(&g_count[r4.x], 1);
            atomicAdd(&g_count[r4.y], 1);
            atomicAdd(&g_count[r4.z], 1);
            atomicAdd(&g_count[r4.w], 1);
        } else {
            for (int q = e; q < E; q++) atomicAdd(&g_count[__ldg(rows + q)], 1);
        }
        return;
    }

    // ---- GEMM part ----
    __shared__ __align__(16) float Xs[8][128];   // [k][row]
    __shared__ __align__(16) float Ws[8][128];   // [k][col]

    const int tid  = threadIdx.x;
    const int trow = tid >> 4;        // 0..15
    const int tcol = tid & 15;        // 0..15
    const int row0 = blockIdx.x * 128;

    u64 acc2[8][4];
#pragma unroll
    for (int i = 0; i < 8; i++)
#pragma unroll
        for (int j = 0; j < 4; j++) acc2[i][j] = 0ull;

    const int lrow = tid >> 1;          // 0..127
    const int lk   = (tid & 1) * 4;     // 0 or 4
    const int wk   = tid >> 5;          // 0..7
    const int wn   = (tid & 31) * 4;    // 0..124

    for (int k0 = 0; k0 < F; k0 += 8) {
        float4 w4 = *(const float4*)(W + (size_t)(k0 + wk) * F + wn);
        *(float4*)&Ws[wk][wn] = w4;
        int grow = row0 + lrow;
        float4 x4 = make_float4(0.f, 0.f, 0.f, 0.f);
        if (grow < N) x4 = *(const float4*)(X + (size_t)grow * F + k0 + lk);
        Xs[lk + 0][lrow] = x4.x;
        Xs[lk + 1][lrow] = x4.y;
        Xs[lk + 2][lrow] = x4.z;
        Xs[lk + 3][lrow] = x4.w;
        __syncthreads();

#pragma unroll
        for (int kk = 0; kk < 8; kk++) {
            float4 a0 = *(const float4*)&Xs[kk][trow * 8];
            float4 a1 = *(const float4*)&Xs[kk][trow * 8 + 4];
            float4 b0 = *(const float4*)&Ws[kk][tcol * 8];
            float4 b1 = *(const float4*)&Ws[kk][tcol * 8 + 4];
            u64 bp[4] = { pack2(b0.x, b0.y), pack2(b0.z, b0.w),
                          pack2(b1.x, b1.y), pack2(b1.z, b1.w) };
            float a[8] = {a0.x, a0.y, a0.z, a0.w, a1.x, a1.y, a1.z, a1.w};
#pragma unroll
            for (int i = 0; i < 8; i++) {
                u64 ap = pack2(a[i], a[i]);
#pragma unroll
                for (int j = 0; j < 4; j++)
                    fma2(acc2[i][j], ap, bp[j]);
            }
        }
        __syncthreads();
    }

    float bv[8];
#pragma unroll
    for (int j = 0; j < 8; j++) bv[j] = bias[tcol * 8 + j];

#pragma unroll
    for (int i = 0; i < 8; i++) {
        int grow = row0 + trow * 8 + i;
        if (grow < N) {
            float2 p0 = unpack2(acc2[i][0]);
            float2 p1 = unpack2(acc2[i][1]);
            float2 p2 = unpack2(acc2[i][2]);
            float2 p3 = unpack2(acc2[i][3]);
            float4 o0, o1;
            o0.x = p0.x + bv[0]; o0.y = p0.y + bv[1];
            o0.z = p1.x + bv[2]; o0.w = p1.y + bv[3];
            o1.x = p2.x + bv[4]; o1.y = p2.y + bv[5];
            o1.z = p3.x + bv[6]; o1.w = p3.y + bv[7];
            *(float4*)(g_H + (size_t)grow * F + tcol * 8)     = o0;
            *(float4*)(g_H + (size_t)grow * F + tcol * 8 + 4) = o1;
        }
    }
}

// ---------------------------------------------------------------------------
// CSR build: self-zeroing per-block scan, merged-tops add, placement
// ---------------------------------------------------------------------------
__global__ void __launch_bounds__(1024) scan_partial_kernel(int N)
{
    int i = blockIdx.x * 1024 + threadIdx.x;
    int v = (i < N) ? g_count[i] : 0;
    if (i < N) g_count[i] = 0;                  // restore zero-invariant
    int lane = threadIdx.x & 31, wid = threadIdx.x >> 5;

    int x = v;
#pragma unroll
    for (int d = 1; d < 32; d <<= 1) {
        int y = __shfl_up_sync(0xffffffffu, x, d);
        if (lane >= d) x += y;
    }
    __shared__ int wsum[32];
    if (lane == 31) wsum[wid] = x;
    __syncthreads();
    if (wid == 0) {
        int w = wsum[lane];
#pragma unroll
        for (int d = 1; d < 32; d <<= 1) {
            int y = __shfl_up_sync(0xffffffffu, w, d);
            if (lane >= d) w += y;
        }
        wsum[lane] = w;
    }
    __syncthreads();
    int base = wid ? wsum[wid - 1] : 0;
    int incl = base + x;
    if (i < N) g_offset[i] = incl - v;          // block-local exclusive
    if (threadIdx.x == 1023) g_part[blockIdx.x] = incl;
}

// adds block-prefix (recomputed in-block from g_part) to every offset
__global__ void __launch_bounds__(1024) scan_add_kernel(int N, int E, int NB)
{
    __shared__ int s[128];
    int t = threadIdx.x;
    if (t < 128) s[t] = (t < NB) ? g_part[t] : 0;
    __syncthreads();
#pragma unroll
    for (int d = 1; d < 128; d <<= 1) {
        int y = (t < 128 && t >= d) ? s[t - d] : 0;
        __syncthreads();
        if (t < 128) s[t] += y;
        __syncthreads();
    }
    int i = blockIdx.x * 1024 + t;
    if (i < N) {
        int b = (int)blockIdx.x;
        int o = g_offset[i] + (b ? s[b - 1] : 0);
        g_offset[i] = o;
        g_woff[i]   = o;
    }
    if (i == 0) g_offset[N] = E;
}

// placement: 2 edges/thread via int2/float2 loads (E even; buffers aligned)
__global__ void __launch_bounds__(256) place_kernel(
    const int* __restrict__ rows, const int* __restrict__ cols,
    const float* __restrict__ vals, int E)
{
    int e = (blockIdx.x * blockDim.x + threadIdx.x) * 2;
    if (e >= E) return;
    if (e + 1 < E) {
        int2   r2 = __ldg((const int2*)(rows + e));
        int2   c2 = __ldg((const int2*)(cols + e));
        float2 v2 = __ldg((const float2*)(vals + e));
        int p0 = atomicAdd(&g_woff[r2.x], 1);
        g_edge[p0] = ((unsigned long long)__float_as_uint(v2.x) << 32) | (unsigned)c2.x;
        int p1 = atomicAdd(&g_woff[r2.y], 1);
        g_edge[p1] = ((unsigned long long)__float_as_uint(v2.y) << 32) | (unsigned)c2.y;
    } else {
        int r = __ldg(rows + e);
        int p = atomicAdd(&g_woff[r], 1);
        g_edge[p] = ((unsigned long long)__float_as_uint(__ldg(vals + e)) << 32) |
                    (unsigned)__ldg(cols + e);
    }
}

// ---------------------------------------------------------------------------
// threefry2x32-partitionable bits for element index j (key = (0,42))
// ---------------------------------------------------------------------------
__device__ __forceinline__ unsigned tf_bits(unsigned j)
{
    const unsigned ks0 = 0u, ks1 = 42u;
    const unsigned ks2 = 0x1BD11BDAu ^ ks0 ^ ks1;
    unsigned x0 = ks0;          // hi32(counter) = 0
    unsigned x1 = j + ks1;
#define TF_R(d) { x0 += x1; x1 = __funnelshift_l(x1, x1, (d)); x1 ^= x0; }
    TF_R(13) TF_R(15) TF_R(26) TF_R(6)
    x0 += ks1; x1 += ks2 + 1u;
    TF_R(17) TF_R(29) TF_R(16) TF_R(24)
    x0 += ks2; x1 += ks0 + 2u;
    TF_R(13) TF_R(15) TF_R(26) TF_R(6)
    x0 += ks0; x1 += ks1 + 3u;
    TF_R(17) TF_R(29) TF_R(16) TF_R(24)
    x0 += ks1; x1 += ks2 + 4u;
    TF_R(13) TF_R(15) TF_R(26) TF_R(6)
    x0 += ks2; x1 += ks0 + 5u;
#undef TF_R
    return x0 ^ x1;
}

__device__ __forceinline__ float drop_apply(float h, unsigned j)
{
    float u = __uint_as_float((tf_bits(j) >> 9) | 0x3f800000u) - 1.0f;
    return (u < 0.9f) ? h * (1.0f / 0.9f) : 0.0f;
}

// ---------------------------------------------------------------------------
// Gather + ReLU + dropout: warp per row.
// ---------------------------------------------------------------------------
__global__ void __launch_bounds__(256) gather_kernel(float* __restrict__ out, int N)
{
    int warp = (blockIdx.x * blockDim.x + threadIdx.x) >> 5;
    int lane = threadIdx.x & 31;
    if (warp >= N) return;
    const int row   = warp;
    const int start = g_offset[row];
    const int end   = g_offset[row + 1];

    float4 acc = make_float4(0.f, 0.f, 0.f, 0.f);

    for (int b = start; b < end; b += 32) {
        int e = b + lane;
        unsigned long long ev = (e < end) ? g_edge[e] : 0ull;
        int cnt = min(32, end - b);
        int i = 0;
        for (; i + 1 < cnt; i += 2) {
            unsigned long long e0 = __shfl_sync(0xffffffffu, ev, i);
            unsigned long long e1 = __shfl_sync(0xffffffffu, ev, i + 1);
            int   c0 = (int)(unsigned)e0;
            int   c1 = (int)(unsigned)e1;
            float v0 = __uint_as_float((unsigned)(e0 >> 32));
            float v1 = __uint_as_float((unsigned)(e1 >> 32));
            float4 m0 = *(const float4*)(g_H + (size_t)c0 * F + lane * 4);
            float4 m1 = *(const float4*)(g_H + (size_t)c1 * F + lane * 4);
            acc.x = fmaf(m0.x, v0, acc.x); acc.y = fmaf(m0.y, v0, acc.y);
            acc.z = fmaf(m0.z, v0, acc.z); acc.w = fmaf(m0.w, v0, acc.w);
            acc.x = fmaf(m1.x, v1, acc.x); acc.y = fmaf(m1.y, v1, acc.y);
            acc.z = fmaf(m1.z, v1, acc.z); acc.w = fmaf(m1.w, v1, acc.w);
        }
        if (i < cnt) {
            unsigned long long e0 = __shfl_sync(0xffffffffu, ev, i);
            int   c0 = (int)(unsigned)e0;
            float v0 = __uint_as_float((unsigned)(e0 >> 32));
            float4 m0 = *(const float4*)(g_H + (size_t)c0 * F + lane * 4);
            acc.x = fmaf(m0.x, v0, acc.x); acc.y = fmaf(m0.y, v0, acc.y);
            acc.z = fmaf(m0.z, v0, acc.z); acc.w = fmaf(m0.w, v0, acc.w);
        }
    }

    acc.x = fmaxf(acc.x, 0.f); acc.y = fmaxf(acc.y, 0.f);
    acc.z = fmaxf(acc.z, 0.f); acc.w = fmaxf(acc.w, 0.f);

    unsigned j0 = (unsigned)row * F + lane * 4;
    acc.x = drop_apply(acc.x, j0 + 0);
    acc.y = drop_apply(acc.y, j0 + 1);
    acc.z = drop_apply(acc.z, j0 + 2);
    acc.w = drop_apply(acc.w, j0 + 3);

    *(float4*)(out + (size_t)row * F + lane * 4) = acc;
}

// ---------------------------------------------------------------------------
extern "C" void kernel_launch(void* const* d_in, const int* in_sizes, int n_in,
                              void* d_out, int out_size)
{
    const float* X    = (const float*)d_in[0];
    const float* W    = (const float*)d_in[1];
    const float* bias = (const float*)d_in[2];
    const int*   rows = (const int*)d_in[3];
    const int*   cols = (const int*)d_in[4];
    const float* vals = (const float*)d_in[5];
    float* out = (float*)d_out;

    const int N  = in_sizes[0] / F;     // 100000
    const int E  = in_sizes[3];         // 1600000
    const int NB = (N + 1023) / 1024;   // 98

    // fused H = X@W + b  AND  row histogram (tail blocks, 4 edges/thread)
    {
        int gemm_blocks = (N + 127) / 128;              // 782
        int hist_blocks = (E + 1023) / 1024;            // 1563
        gemm_hist_kernel<<<gemm_blocks + hist_blocks, 256>>>(
            X, W, bias, rows, N, E, gemm_blocks);
    }

    // CSR offsets (2 launches) + placement (2 edges/thread)
    scan_partial_kernel<<<NB, 1024>>>(N);
    scan_add_kernel<<<NB, 1024>>>(N, E, NB);
    place_kernel<<<(E / 2 + 255) / 256, 256>>>(rows, cols, vals, E);

    // fused gather + relu + dropout
    {
        int grid = (N * 32 + 255) / 256;
        gather_kernel<<<grid, 256>>>(out, N);
    }
}

// round 15
// speedup vs baseline: 1.2266x; 1.0335x over previous
#include <cuda_runtime.h>
#include <cuda_fp16.h>
#include <cstdint>
#include <cstddef>

#define F 128
#define N_MAX 100000
#define E_MAX 1600000
#define NB_MAX 128   // ceil(N_MAX/1024) = 98

typedef unsigned long long u64;

// ------------------------- static scratch (no allocs) ----------------------
__device__ __align__(16) __half g_Hh[(size_t)N_MAX * F];        // X@W+b in fp16
__device__ unsigned long long g_edge[E_MAX];                    // packed (val<<32 | col), CSR-ordered
__device__ int g_count[N_MAX];                                  // degree histogram (zero-invariant)
__device__ int g_offset[N_MAX + 1];                             // CSR row offsets
__device__ int g_woff[N_MAX];                                   // placement cursors
__device__ int g_part[NB_MAX];                                  // scan block partials

// ------------------------- bit-cast helpers --------------------------------
__device__ __forceinline__ unsigned h2_as_u32(__half2 h)
{
    union { __half2 h; unsigned u; } c;
    c.h = h;
    return c.u;
}
__device__ __forceinline__ __half2 u32_as_h2(unsigned u)
{
    union { unsigned u; __half2 h; } c;
    c.u = u;
    return c.h;
}

// ------------------------- f32x2 packed FMA helpers ------------------------
__device__ __forceinline__ u64 pack2(float lo, float hi)
{
    u64 r;
    asm("mov.b64 %0, {%1, %2};" : "=l"(r) : "f"(lo), "f"(hi));
    return r;
}
__device__ __forceinline__ void fma2(u64& d, u64 a, u64 b)
{
    asm("fma.rn.f32x2 %0, %1, %2, %0;" : "+l"(d) : "l"(a), "l"(b));
}
__device__ __forceinline__ float2 unpack2(u64 v)
{
    float2 f;
    asm("mov.b64 {%0, %1}, %2;" : "=f"(f.x), "=f"(f.y) : "l"(v));
    return f;
}

// ---------------------------------------------------------------------------
// Fused: GEMM (blocks [0, gemm_blocks)) + row histogram (tail blocks).
// GEMM: H[N,128] = X[N,128] @ W[128,128] + b[128], stored as fp16
//   BM=128, BN=128, BK=8, 256 threads, 8x8 thread tile, packed f32x2 FMA.
// Hist tail: 4 edges/thread via int4 loads.
// ---------------------------------------------------------------------------
__global__ void __launch_bounds__(256) gemm_hist_kernel(
    const float* __restrict__ X, const float* __restrict__ W,
    const float* __restrict__ bias, const int* __restrict__ rows,
    int N, int E, int gemm_blocks)
{
    if ((int)blockIdx.x >= gemm_blocks) {
        int e = (((int)blockIdx.x - gemm_blocks) * 256 + threadIdx.x) * 4;
        if (e + 3 < E) {
            int4 r4 = __ldg((const int4*)(rows + e));
            atomicAdd(&g_count[r4.x], 1);
            atomicAdd(&g_count[r4.y], 1);
            atomicAdd(&g_count[r4.z], 1);
            atomicAdd(&g_count[r4.w], 1);
        } else {
            for (int q = e; q < E; q++) atomicAdd(&g_count[__ldg(rows + q)], 1);
        }
        return;
    }

    // ---- GEMM part ----
    __shared__ __align__(16) float Xs[8][128];   // [k][row]
    __shared__ __align__(16) float Ws[8][128];   // [k][col]

    const int tid  = threadIdx.x;
    const int trow = tid >> 4;        // 0..15
    const int tcol = tid & 15;        // 0..15
    const int row0 = blockIdx.x * 128;

    u64 acc2[8][4];
#pragma unroll
    for (int i = 0; i < 8; i++)
#pragma unroll
        for (int j = 0; j < 4; j++) acc2[i][j] = 0ull;

    const int lrow = tid >> 1;          // 0..127
    const int lk   = (tid & 1) * 4;     // 0 or 4
    const int wk   = tid >> 5;          // 0..7
    const int wn   = (tid & 31) * 4;    // 0..124

    for (int k0 = 0; k0 < F; k0 += 8) {
        float4 w4 = *(const float4*)(W + (size_t)(k0 + wk) * F + wn);
        *(float4*)&Ws[wk][wn] = w4;
        int grow = row0 + lrow;
        float4 x4 = make_float4(0.f, 0.f, 0.f, 0.f);
        if (grow < N) x4 = *(const float4*)(X + (size_t)grow * F + k0 + lk);
        Xs[lk + 0][lrow] = x4.x;
        Xs[lk + 1][lrow] = x4.y;
        Xs[lk + 2][lrow] = x4.z;
        Xs[lk + 3][lrow] = x4.w;
        __syncthreads();

#pragma unroll
        for (int kk = 0; kk < 8; kk++) {
            float4 a0 = *(const float4*)&Xs[kk][trow * 8];
            float4 a1 = *(const float4*)&Xs[kk][trow * 8 + 4];
            float4 b0 = *(const float4*)&Ws[kk][tcol * 8];
            float4 b1 = *(const float4*)&Ws[kk][tcol * 8 + 4];
            u64 bp[4] = { pack2(b0.x, b0.y), pack2(b0.z, b0.w),
                          pack2(b1.x, b1.y), pack2(b1.z, b1.w) };
            float a[8] = {a0.x, a0.y, a0.z, a0.w, a1.x, a1.y, a1.z, a1.w};
#pragma unroll
            for (int i = 0; i < 8; i++) {
                u64 ap = pack2(a[i], a[i]);
#pragma unroll
                for (int j = 0; j < 4; j++)
                    fma2(acc2[i][j], ap, bp[j]);
            }
        }
        __syncthreads();
    }

    float bv[8];
#pragma unroll
    for (int j = 0; j < 8; j++) bv[j] = bias[tcol * 8 + j];

#pragma unroll
    for (int i = 0; i < 8; i++) {
        int grow = row0 + trow * 8 + i;
        if (grow < N) {
            float2 p0 = unpack2(acc2[i][0]);
            float2 p1 = unpack2(acc2[i][1]);
            float2 p2 = unpack2(acc2[i][2]);
            float2 p3 = unpack2(acc2[i][3]);
            __half2 h0 = __floats2half2_rn(p0.x + bv[0], p0.y + bv[1]);
            __half2 h1 = __floats2half2_rn(p1.x + bv[2], p1.y + bv[3]);
            __half2 h2 = __floats2half2_rn(p2.x + bv[4], p2.y + bv[5]);
            __half2 h3 = __floats2half2_rn(p3.x + bv[6], p3.y + bv[7]);
            uint4 pk;
            pk.x = h2_as_u32(h0); pk.y = h2_as_u32(h1);
            pk.z = h2_as_u32(h2); pk.w = h2_as_u32(h3);
            *(uint4*)(g_Hh + (size_t)grow * F + tcol * 8) = pk;   // 8 halfs = 16B
        }
    }
}

// ---------------------------------------------------------------------------
// CSR build: self-zeroing per-block scan, merged-tops add, placement
// ---------------------------------------------------------------------------
__global__ void __launch_bounds__(1024) scan_partial_kernel(int N)
{
    int i = blockIdx.x * 1024 + threadIdx.x;
    int v = (i < N) ? g_count[i] : 0;
    if (i < N) g_count[i] = 0;                  // restore zero-invariant
    int lane = threadIdx.x & 31, wid = threadIdx.x >> 5;

    int x = v;
#pragma unroll
    for (int d = 1; d < 32; d <<= 1) {
        int y = __shfl_up_sync(0xffffffffu, x, d);
        if (lane >= d) x += y;
    }
    __shared__ int wsum[32];
    if (lane == 31) wsum[wid] = x;
    __syncthreads();
    if (wid == 0) {
        int w = wsum[lane];
#pragma unroll
        for (int d = 1; d < 32; d <<= 1) {
            int y = __shfl_up_sync(0xffffffffu, w, d);
            if (lane >= d) w += y;
        }
        wsum[lane] = w;
    }
    __syncthreads();
    int base = wid ? wsum[wid - 1] : 0;
    int incl = base + x;
    if (i < N) g_offset[i] = incl - v;          // block-local exclusive
    if (threadIdx.x == 1023) g_part[blockIdx.x] = incl;
}

__global__ void __launch_bounds__(1024) scan_add_kernel(int N, int E, int NB)
{
    __shared__ int s[128];
    int t = threadIdx.x;
    if (t < 128) s[t] = (t < NB) ? g_part[t] : 0;
    __syncthreads();
#pragma unroll
    for (int d = 1; d < 128; d <<= 1) {
        int y = (t < 128 && t >= d) ? s[t - d] : 0;
        __syncthreads();
        if (t < 128) s[t] += y;
        __syncthreads();
    }
    int i = blockIdx.x * 1024 + t;
    if (i < N) {
        int b = (int)blockIdx.x;
        int o = g_offset[i] + (b ? s[b - 1] : 0);
        g_offset[i] = o;
        g_woff[i]   = o;
    }
    if (i == 0) g_offset[N] = E;
}

// placement: 4 edges/thread via int4/float4 loads (issue-limited; more ILP)
__global__ void __launch_bounds__(256) place_kernel(
    const int* __restrict__ rows, const int* __restrict__ cols,
    const float* __restrict__ vals, int E)
{
    int e = (blockIdx.x * blockDim.x + threadIdx.x) * 4;
    if (e >= E) return;
    if (e + 3 < E) {
        int4   r4 = __ldg((const int4*)(rows + e));
        int4   c4 = __ldg((const int4*)(cols + e));
        float4 v4 = __ldg((const float4*)(vals + e));
        int p0 = atomicAdd(&g_woff[r4.x], 1);
        int p1 = atomicAdd(&g_woff[r4.y], 1);
        int p2 = atomicAdd(&g_woff[r4.z], 1);
        int p3 = atomicAdd(&g_woff[r4.w], 1);
        g_edge[p0] = ((unsigned long long)__float_as_uint(v4.x) << 32) | (unsigned)c4.x;
        g_edge[p1] = ((unsigned long long)__float_as_uint(v4.y) << 32) | (unsigned)c4.y;
        g_edge[p2] = ((unsigned long long)__float_as_uint(v4.z) << 32) | (unsigned)c4.z;
        g_edge[p3] = ((unsigned long long)__float_as_uint(v4.w) << 32) | (unsigned)c4.w;
    } else {
        for (int q = e; q < E; q++) {
            int r = __ldg(rows + q);
            int p = atomicAdd(&g_woff[r], 1);
            g_edge[p] = ((unsigned long long)__float_as_uint(__ldg(vals + q)) << 32) |
                        (unsigned)__ldg(cols + q);
        }
    }
}

// ---------------------------------------------------------------------------
// threefry2x32-partitionable bits for element index j (key = (0,42))
// ---------------------------------------------------------------------------
__device__ __forceinline__ unsigned tf_bits(unsigned j)
{
    const unsigned ks0 = 0u, ks1 = 42u;
    const unsigned ks2 = 0x1BD11BDAu ^ ks0 ^ ks1;
    unsigned x0 = ks0;          // hi32(counter) = 0
    unsigned x1 = j + ks1;
#define TF_R(d) { x0 += x1; x1 = __funnelshift_l(x1, x1, (d)); x1 ^= x0; }
    TF_R(13) TF_R(15) TF_R(26) TF_R(6)
    x0 += ks1; x1 += ks2 + 1u;
    TF_R(17) TF_R(29) TF_R(16) TF_R(24)
    x0 += ks2; x1 += ks0 + 2u;
    TF_R(13) TF_R(15) TF_R(26) TF_R(6)
    x0 += ks0; x1 += ks1 + 3u;
    TF_R(17) TF_R(29) TF_R(16) TF_R(24)
    x0 += ks1; x1 += ks2 + 4u;
    TF_R(13) TF_R(15) TF_R(26) TF_R(6)
    x0 += ks2; x1 += ks0 + 5u;
#undef TF_R
    return x0 ^ x1;
}

__device__ __forceinline__ float drop_apply(float h, unsigned j)
{
    float u = __uint_as_float((tf_bits(j) >> 9) | 0x3f800000u) - 1.0f;
    return (u < 0.9f) ? h * (1.0f / 0.9f) : 0.0f;
}

// ---------------------------------------------------------------------------
// Gather + ReLU + dropout: warp per row; fp16 H (half traffic), fp32 accum.
// ---------------------------------------------------------------------------
__global__ void __launch_bounds__(256) gather_kernel(float* __restrict__ out, int N)
{
    int warp = (blockIdx.x * blockDim.x + threadIdx.x) >> 5;
    int lane = threadIdx.x & 31;
    if (warp >= N) return;
    const int row   = warp;
    const int start = g_offset[row];
    const int end   = g_offset[row + 1];

    float4 acc = make_float4(0.f, 0.f, 0.f, 0.f);

    for (int b = start; b < end; b += 32) {
        int e = b + lane;
        unsigned long long ev = (e < end) ? g_edge[e] : 0ull;
        int cnt = min(32, end - b);
        int i = 0;
        for (; i + 1 < cnt; i += 2) {
            unsigned long long e0 = __shfl_sync(0xffffffffu, ev, i);
            unsigned long long e1 = __shfl_sync(0xffffffffu, ev, i + 1);
            int   c0 = (int)(unsigned)e0;
            int   c1 = (int)(unsigned)e1;
            float v0 = __uint_as_float((unsigned)(e0 >> 32));
            float v1 = __uint_as_float((unsigned)(e1 >> 32));
            uint2 u0 = *(const uint2*)(g_Hh + (size_t)c0 * F + lane * 4);
            uint2 u1 = *(const uint2*)(g_Hh + (size_t)c1 * F + lane * 4);
            float2 f0a = __half22float2(u32_as_h2(u0.x));
            float2 f0b = __half22float2(u32_as_h2(u0.y));
            float2 f1a = __half22float2(u32_as_h2(u1.x));
            float2 f1b = __half22float2(u32_as_h2(u1.y));
            acc.x = fmaf(f0a.x, v0, acc.x); acc.y = fmaf(f0a.y, v0, acc.y);
            acc.z = fmaf(f0b.x, v0, acc.z); acc.w = fmaf(f0b.y, v0, acc.w);
            acc.x = fmaf(f1a.x, v1, acc.x); acc.y = fmaf(f1a.y, v1, acc.y);
            acc.z = fmaf(f1b.x, v1, acc.z); acc.w = fmaf(f1b.y, v1, acc.w);
        }
        if (i < cnt) {
            unsigned long long e0 = __shfl_sync(0xffffffffu, ev, i);
            int   c0 = (int)(unsigned)e0;
            float v0 = __uint_as_float((unsigned)(e0 >> 32));
            uint2 u0 = *(const uint2*)(g_Hh + (size_t)c0 * F + lane * 4);
            float2 f0a = __half22float2(u32_as_h2(u0.x));
            float2 f0b = __half22float2(u32_as_h2(u0.y));
            acc.x = fmaf(f0a.x, v0, acc.x); acc.y = fmaf(f0a.y, v0, acc.y);
            acc.z = fmaf(f0b.x, v0, acc.z); acc.w = fmaf(f0b.y, v0, acc.w);
        }
    }

    acc.x = fmaxf(acc.x, 0.f); acc.y = fmaxf(acc.y, 0.f);
    acc.z = fmaxf(acc.z, 0.f); acc.w = fmaxf(acc.w, 0.f);

    unsigned j0 = (unsigned)row * F + lane * 4;
    acc.x = drop_apply(acc.x, j0 + 0);
    acc.y = drop_apply(acc.y, j0 + 1);
    acc.z = drop_apply(acc.z, j0 + 2);
    acc.w = drop_apply(acc.w, j0 + 3);

    *(float4*)(out + (size_t)row * F + lane * 4) = acc;
}

// ---------------------------------------------------------------------------
extern "C" void kernel_launch(void* const* d_in, const int* in_sizes, int n_in,
                              void* d_out, int out_size)
{
    const float* X    = (const float*)d_in[0];
    const float* W    = (const float*)d_in[1];
    const float* bias = (const float*)d_in[2];
    const int*   rows = (const int*)d_in[3];
    const int*   cols = (const int*)d_in[4];
    const float* vals = (const float*)d_in[5];
    float* out = (float*)d_out;

    const int N  = in_sizes[0] / F;     // 100000
    const int E  = in_sizes[3];         // 1600000
    const int NB = (N + 1023) / 1024;   // 98

    // fused H = X@W + b (fp16 store)  AND  row histogram (tail, 4 edges/thr)
    {
        int gemm_blocks = (N + 127) / 128;              // 782
        int hist_blocks = (E + 1023) / 1024;            // 1563
        gemm_hist_kernel<<<gemm_blocks + hist_blocks, 256>>>(
            X, W, bias, rows, N, E, gemm_blocks);
    }

    // CSR offsets + placement (4 edges/thread)
    scan_partial_kernel<<<NB, 1024>>>(N);
    scan_add_kernel<<<NB, 1024>>>(N, E, NB);
    place_kernel<<<(E / 4 + 255) / 256, 256>>>(rows, cols, vals, E);

    // fused gather (fp16 H) + relu + dropout
    {
        int grid = (N * 32 + 255) / 256;
        gather_kernel<<<grid, 256>>>(out, N);
    }
}